// round 10
// baseline (speedup 1.0000x reference)
#include <cuda_runtime.h>

// Scratch (graph-capturable: __device__ globals, zero at module load).
// g_bmL: per-LEAF touched bitmap, 8M bits = 262144 words. Built by k_scatter
//        (atomicOr); self-cleared by each k_prop block after use.
#define BML_WORDS 262144
__device__ unsigned g_bmL[BML_WORDS];
__device__ unsigned char g_f13[1024];        // level-13 touched flags
__device__ unsigned g_done;                  // last-block counter (self-reset)

// Scatter leaf values into dst; mark per-leaf bitmap. 2 updates per thread.
__global__ void __launch_bounds__(256) k_scatter(const int2* __restrict__ idx,
                                                 const float2* __restrict__ vals,
                                                 float* __restrict__ dst, int n2,
                                                 unsigned cap) {
    int i = blockIdx.x * blockDim.x + threadIdx.x;
    if (i >= n2) return;
    int2   id = __ldcs(&idx[i]);
    float2 v  = __ldcs(&vals[i]);
    dst[cap + (unsigned)id.x] = v.x;
    dst[cap + (unsigned)id.y] = v.y;
    atomicOr(&g_bmL[(unsigned)id.x >> 5], 1u << ((unsigned)id.x & 31u));
    atomicOr(&g_bmL[(unsigned)id.y >> 5], 1u << ((unsigned)id.y & 31u));
}

// Fused: leaf merge + propagation levels 1..23. Each block owns 4096 level-1
// nodes (8192 leaves; subtree up to one level-13 node). All loads are
// UNCONDITIONAL (selects resolve touched-ness). The per-block upper-subtree
// src values (levels 2..13 = 4095 floats) are PREFETCHED into smem before the
// level-1 phase so the barrier ladder never touches global memory. Config
// pinned to 4 blocks/SM (2048 threads/SM; R8 showed residency dominates).
// The LAST block runs levels 14..23 (threadFenceReduction pattern).
#define CHUNK 4096
#define PTHREADS 512

__global__ void __launch_bounds__(PTHREADS, 4) k_prop(float* __restrict__ dst,
                                                      const float* __restrict__ src,
                                                      unsigned cap) {
    __shared__ __align__(16) float vA[CHUNK];
    __shared__ __align__(16) float vB[CHUNK / 2];
    __shared__ __align__(16) float sPre[CHUNK];        // src levels 2..13 (4095 used)
    __shared__ __align__(16) unsigned char fA[CHUNK];
    __shared__ __align__(16) unsigned char fB[CHUNK / 2];
    __shared__ unsigned s_islast;
    unsigned b = blockIdx.x, t = threadIdx.x;
    unsigned lvl1 = cap >> 1;                 // 4M level-1 nodes
    unsigned base = b * CHUNK;

    // Prefetch src for levels 2..13 into sPre (coalesced; overlaps level-1 phase).
    // Layout: level L at offset off_L, off_2=0, off_{L+1}=off_L+n_L; n_L=CHUNK>>(L-1).
    {
        unsigned off = 0;
        #pragma unroll
        for (int L = 2; L <= 13; L++) {
            unsigned nL = CHUNK >> (L - 1);
            for (unsigned j = t; j < nL; j += PTHREADS)
                sPre[off + j] = __ldcs(src + (cap >> L) + b * nL + j);
            off += nL;
        }
    }

    // Level 0+1: two independent 4-node groups per thread (8 nodes, 16 leaves).
    #pragma unroll
    for (unsigned g = 0; g < 2; g++) {
        unsigned k = (t + g * PTHREADS) * 4u;          // local index in [0, CHUNK)
        unsigned j = base + k;                         // level-1 node (4-aligned)
        unsigned leaf = 2u * j;                        // leaf (8-aligned)
        unsigned bits = (g_bmL[leaf >> 5] >> (leaf & 31u)) & 0xFFu;
        unsigned p = lvl1 + j;
        const float4* s4 = (const float4*)(src + cap) + (leaf >> 2);
        float4*       d4 = (float4*)(dst + cap) + (leaf >> 2);
        float4 s0 = __ldcs(&s4[0]), s1 = __ldcs(&s4[1]);
        float4 d0 = d4[0], d1 = d4[1];                 // unconditional (L2 dirty)
        float4 orig = __ldcs((const float4*)(src + p));
        float4 m0, m1;                                 // merged leaves
        m0.x = (bits & 1u)   ? d0.x : s0.x;
        m0.y = (bits & 2u)   ? d0.y : s0.y;
        m0.z = (bits & 4u)   ? d0.z : s0.z;
        m0.w = (bits & 8u)   ? d0.w : s0.w;
        m1.x = (bits & 16u)  ? d1.x : s1.x;
        m1.y = (bits & 32u)  ? d1.y : s1.y;
        m1.z = (bits & 64u)  ? d1.z : s1.z;
        m1.w = (bits & 128u) ? d1.w : s1.w;
        __stcs(&d4[0], m0); __stcs(&d4[1], m1);        // streaming, coalesced
        bool t0 = bits & 0x03u, t1 = bits & 0x0Cu,
             t2 = bits & 0x30u, t3 = bits & 0xC0u;
        float4 v;
        v.x = t0 ? m0.x + m0.y : orig.x;
        v.y = t1 ? m0.z + m0.w : orig.y;
        v.z = t2 ? m1.x + m1.y : orig.z;
        v.w = t3 ? m1.z + m1.w : orig.w;
        __stcs((float4*)(dst + p), v);                 // final, never re-read
        vA[k] = v.x; vA[k + 1] = v.y; vA[k + 2] = v.z; vA[k + 3] = v.w;
        fA[k] = t0;  fA[k + 1] = t1;  fA[k + 2] = t2;  fA[k + 3] = t3;
    }
    __syncthreads();

    // Self-clear this block's 256 bitmap words for the next replay.
    if (t < 256u) g_bmL[b * 256u + t] = 0u;

    // Level 2: n=2048, 4 nodes/thread, fully vectorized, src from sPre[0..2047].
    {
        unsigned j0 = 4u * t;                          // local node index
        float4 c0 = *(const float4*)(vA + 2u * j0);
        float4 c1 = *(const float4*)(vA + 2u * j0 + 4u);
        unsigned w0 = *(const unsigned*)(fA + 2u * j0);
        unsigned w1 = *(const unsigned*)(fA + 2u * j0 + 4u);
        unsigned p = (cap >> 2) + b * 2048u + j0;
        float4 s = *(const float4*)(sPre + j0);
        bool t0 = (w0 & 0x0000FFFFu) != 0u, t1 = (w0 & 0xFFFF0000u) != 0u,
             t2 = (w1 & 0x0000FFFFu) != 0u, t3 = (w1 & 0xFFFF0000u) != 0u;
        float4 v;
        v.x = t0 ? c0.x + c0.y : s.x;
        v.y = t1 ? c0.z + c0.w : s.y;
        v.z = t2 ? c1.x + c1.y : s.z;
        v.w = t3 ? c1.z + c1.w : s.w;
        __stcs((float4*)(dst + p), v);
        *(float4*)(vB + j0) = v;
        uchar4 f; f.x = t0; f.y = t1; f.z = t2; f.w = t3;
        *(uchar4*)(fB + j0) = f;
    }
    __syncthreads();

    // Level 3: n=1024, 2 nodes/thread, src from sPre[2048..3071].
    {
        unsigned j0 = 2u * t;
        float4 c = *(const float4*)(vB + 2u * j0);
        unsigned w = *(const unsigned*)(fB + 2u * j0);
        unsigned p = (cap >> 3) + b * 1024u + j0;
        float2 s = *(const float2*)(sPre + 2048u + j0);
        bool t0 = (w & 0x0000FFFFu) != 0u, t1 = (w & 0xFFFF0000u) != 0u;
        float2 v;
        v.x = t0 ? c.x + c.y : s.x;
        v.y = t1 ? c.z + c.w : s.y;
        *(float2*)(dst + p) = v;
        vA[j0] = v.x; vA[j0 + 1] = v.y;
        fA[j0] = t0;  fA[j0 + 1] = t1;
    }
    __syncthreads();

    // Levels 4..13 (node counts 512 .. 1 per block), src from sPre, no global
    // reads inside the barrier ladder.
    float* vin = vA;  float* vout = vB;
    unsigned char* fin = fA; unsigned char* fout = fB;
    unsigned n = 512;
    unsigned soff = 3072;                     // sPre offset of level 4
    for (int L = 4; L <= 13; L++) {
        if (t < n) {
            unsigned j = t;
            unsigned p = (cap >> L) + b * n + j;
            bool tt = fin[2 * j] | fin[2 * j + 1];
            float v = tt ? vin[2 * j] + vin[2 * j + 1] : sPre[soff + j];
            dst[p] = v;
            vout[j] = v; fout[j] = (unsigned char)tt;
        }
        __syncthreads();
        soff += n; n >>= 1;
        float* tv = vin; vin = vout; vout = tv;
        unsigned char* tf = fin; fin = fout; fout = tf;
    }
    if (t == 0) g_f13[b] = fin[0];            // this subtree's level-13 flag

    // ---- last-block-done: the final block runs levels 14..23 ----
    __threadfence();                          // publish dst level-13 + g_f13
    __syncthreads();
    if (t == 0) {
        unsigned x = atomicAdd(&g_done, 1u);
        s_islast = (x == gridDim.x - 1u);
    }
    __syncthreads();
    if (!s_islast) return;
    __threadfence();                          // acquire other blocks' writes

    // Tail prefetch: src[0..1024) into sPre (covers levels 14..23 originals).
    if (t < 512u) {
        sPre[t] = __ldcs(src + t);
        sPre[512u + t] = __ldcs(src + 512u + t);
    }
    // Level 14: 512 nodes, children = level-13 values in dst (indices 1024+).
    if (t < 512u) {
        bool tt = g_f13[2 * t] | g_f13[2 * t + 1];
        unsigned p = 512u + t;
        float v = tt ? dst[2 * p] + dst[2 * p + 1] : sPre[p];  // own-thread sPre
        dst[p] = v;
        vA[t] = v; fA[t] = (unsigned char)tt;
    }
    __syncthreads();
    // Levels 15..23 (256 nodes down to the root), all in smem.
    for (unsigned m = 256; m >= 1; m >>= 1) {
        bool tt = false; float v = 0.0f;
        if (t < m) {
            tt = fA[2 * t] | fA[2 * t + 1];
            unsigned pp = m + t;
            v = tt ? vA[2 * t] + vA[2 * t + 1] : sPre[pp];
            dst[pp] = v;
        }
        __syncthreads();
        if (t < m) { vA[t] = v; fA[t] = (unsigned char)tt; }
        __syncthreads();
    }
    if (t == 0) {
        dst[0] = sPre[0];                     // untouched slot 0
        g_done = 0u;                          // reset for next replay
    }
}

extern "C" void kernel_launch(void* const* d_in, const int* in_sizes, int n_in,
                              void* d_out, int out_size) {
    // tree_values matches out_size; remaining two (metadata order) are
    // indices (int32) then values (float32).
    int ti = 0;
    for (int i = 0; i < n_in; i++) if (in_sizes[i] == out_size) { ti = i; break; }
    int others[2]; int c = 0;
    for (int i = 0; i < n_in && c < 2; i++) if (i != ti) others[c++] = i;

    const float* tree_in = (const float*)d_in[ti];
    const int*   indices = (const int*)d_in[others[0]];
    const float* values  = (const float*)d_in[others[1]];
    float* out = (float*)d_out;

    unsigned total = (unsigned)out_size;      // 16,777,216
    unsigned cap   = total >> 1;              // 8,388,608 = 2^23
    int n = in_sizes[others[0]];              // 1,048,576

    int n2 = n >> 1;                          // 2 updates per thread
    k_scatter<<<(n2 + 255) / 256, 256>>>((const int2*)indices,
                                         (const float2*)values, out, n2, cap);
    unsigned nblocks = (cap >> 1) / CHUNK;    // 1024
    k_prop<<<nblocks, PTHREADS>>>(out, tree_in, cap);
}

// round 11
// speedup vs baseline: 1.0904x; 1.0904x over previous
#include <cuda_runtime.h>

// Scratch (graph-capturable: __device__ globals, zero at module load).
// g_bmL: per-LEAF touched bitmap, 8M bits = 262144 words. Built by k_scatter
//        (atomicOr); self-cleared by each k_prop block after use.
#define BML_WORDS 262144
__device__ unsigned g_bmL[BML_WORDS];
__device__ unsigned char g_f13[1024];        // level-13 touched flags
__device__ unsigned g_done;                  // last-block counter (self-reset)

// Scatter leaf values into dst; mark per-leaf bitmap. 2 updates per thread.
// Triggers the dependent k_prop launch immediately (PDL): k_prop's src-side
// prefetch is independent of the scatter and overlaps with it.
__global__ void __launch_bounds__(256) k_scatter(const int2* __restrict__ idx,
                                                 const float2* __restrict__ vals,
                                                 float* __restrict__ dst, int n2,
                                                 unsigned cap) {
    cudaTriggerProgrammaticLaunchCompletion();
    int i = blockIdx.x * blockDim.x + threadIdx.x;
    if (i >= n2) return;
    int2   id = __ldcs(&idx[i]);
    float2 v  = __ldcs(&vals[i]);
    dst[cap + (unsigned)id.x] = v.x;
    dst[cap + (unsigned)id.y] = v.y;
    atomicOr(&g_bmL[(unsigned)id.x >> 5], 1u << ((unsigned)id.x & 31u));
    atomicOr(&g_bmL[(unsigned)id.y >> 5], 1u << ((unsigned)id.y & 31u));
}

// Fused: leaf merge + propagation levels 1..23. Each block owns 4096 level-1
// nodes (8192 leaves; subtree up to one level-13 node). Launched with PDL:
// phase A (src upper-subtree prefetch into smem) runs CONCURRENTLY with
// k_scatter; cudaGridDependencySynchronize() gates phase B (bitmap + dst
// reads). All loads unconditional; 4 blocks/SM pinned (2048 threads/SM).
// The LAST block runs levels 14..23 (threadFenceReduction pattern).
#define CHUNK 4096
#define PTHREADS 512

__global__ void __launch_bounds__(PTHREADS, 4) k_prop(float* __restrict__ dst,
                                                      const float* __restrict__ src,
                                                      unsigned cap) {
    __shared__ __align__(16) float vA[CHUNK];
    __shared__ __align__(16) float vB[CHUNK / 2];
    __shared__ __align__(16) float sPre[CHUNK];        // src levels 2..13 (4095 used)
    __shared__ __align__(16) unsigned char fA[CHUNK];
    __shared__ __align__(16) unsigned char fB[CHUNK / 2];
    __shared__ unsigned s_islast;
    unsigned b = blockIdx.x, t = threadIdx.x;
    unsigned lvl1 = cap >> 1;                 // 4M level-1 nodes
    unsigned base = b * CHUNK;

    // ---- Phase A (overlaps k_scatter): prefetch src levels 2..13 into sPre.
    // Layout: level L at offset off_L, off_2=0, off_{L+1}=off_L+n_L.
    {
        unsigned off = 0;
        #pragma unroll
        for (int L = 2; L <= 13; L++) {
            unsigned nL = CHUNK >> (L - 1);
            for (unsigned j = t; j < nL; j += PTHREADS)
                sPre[off + j] = __ldcs(src + (cap >> L) + b * nL + j);
            off += nL;
        }
    }

    // ---- Gate: wait for k_scatter's leaf writes + bitmap to be visible.
    cudaGridDependencySynchronize();

    // Level 0+1: two independent 4-node groups per thread (8 nodes, 16 leaves).
    #pragma unroll
    for (unsigned g = 0; g < 2; g++) {
        unsigned k = (t + g * PTHREADS) * 4u;          // local index in [0, CHUNK)
        unsigned j = base + k;                         // level-1 node (4-aligned)
        unsigned leaf = 2u * j;                        // leaf (8-aligned)
        unsigned bits = (g_bmL[leaf >> 5] >> (leaf & 31u)) & 0xFFu;
        unsigned p = lvl1 + j;
        const float4* s4 = (const float4*)(src + cap) + (leaf >> 2);
        float4*       d4 = (float4*)(dst + cap) + (leaf >> 2);
        float4 s0 = __ldcs(&s4[0]), s1 = __ldcs(&s4[1]);
        float4 d0 = d4[0], d1 = d4[1];                 // unconditional (L2 dirty)
        float4 orig = __ldcs((const float4*)(src + p));
        float4 m0, m1;                                 // merged leaves
        m0.x = (bits & 1u)   ? d0.x : s0.x;
        m0.y = (bits & 2u)   ? d0.y : s0.y;
        m0.z = (bits & 4u)   ? d0.z : s0.z;
        m0.w = (bits & 8u)   ? d0.w : s0.w;
        m1.x = (bits & 16u)  ? d1.x : s1.x;
        m1.y = (bits & 32u)  ? d1.y : s1.y;
        m1.z = (bits & 64u)  ? d1.z : s1.z;
        m1.w = (bits & 128u) ? d1.w : s1.w;
        __stcs(&d4[0], m0); __stcs(&d4[1], m1);        // streaming, coalesced
        bool t0 = bits & 0x03u, t1 = bits & 0x0Cu,
             t2 = bits & 0x30u, t3 = bits & 0xC0u;
        float4 v;
        v.x = t0 ? m0.x + m0.y : orig.x;
        v.y = t1 ? m0.z + m0.w : orig.y;
        v.z = t2 ? m1.x + m1.y : orig.z;
        v.w = t3 ? m1.z + m1.w : orig.w;
        __stcs((float4*)(dst + p), v);                 // final, never re-read
        vA[k] = v.x; vA[k + 1] = v.y; vA[k + 2] = v.z; vA[k + 3] = v.w;
        fA[k] = t0;  fA[k + 1] = t1;  fA[k + 2] = t2;  fA[k + 3] = t3;
    }
    __syncthreads();

    // Self-clear this block's 256 bitmap words for the next replay.
    if (t < 256u) g_bmL[b * 256u + t] = 0u;

    // Level 2: n=2048, 4 nodes/thread, fully vectorized, src from sPre[0..2047].
    {
        unsigned j0 = 4u * t;                          // local node index
        float4 c0 = *(const float4*)(vA + 2u * j0);
        float4 c1 = *(const float4*)(vA + 2u * j0 + 4u);
        unsigned w0 = *(const unsigned*)(fA + 2u * j0);
        unsigned w1 = *(const unsigned*)(fA + 2u * j0 + 4u);
        unsigned p = (cap >> 2) + b * 2048u + j0;
        float4 s = *(const float4*)(sPre + j0);
        bool t0 = (w0 & 0x0000FFFFu) != 0u, t1 = (w0 & 0xFFFF0000u) != 0u,
             t2 = (w1 & 0x0000FFFFu) != 0u, t3 = (w1 & 0xFFFF0000u) != 0u;
        float4 v;
        v.x = t0 ? c0.x + c0.y : s.x;
        v.y = t1 ? c0.z + c0.w : s.y;
        v.z = t2 ? c1.x + c1.y : s.z;
        v.w = t3 ? c1.z + c1.w : s.w;
        __stcs((float4*)(dst + p), v);
        *(float4*)(vB + j0) = v;
        uchar4 f; f.x = t0; f.y = t1; f.z = t2; f.w = t3;
        *(uchar4*)(fB + j0) = f;
    }
    __syncthreads();

    // Level 3: n=1024, 2 nodes/thread, src from sPre[2048..3071].
    {
        unsigned j0 = 2u * t;
        float4 c = *(const float4*)(vB + 2u * j0);
        unsigned w = *(const unsigned*)(fB + 2u * j0);
        unsigned p = (cap >> 3) + b * 1024u + j0;
        float2 s = *(const float2*)(sPre + 2048u + j0);
        bool t0 = (w & 0x0000FFFFu) != 0u, t1 = (w & 0xFFFF0000u) != 0u;
        float2 v;
        v.x = t0 ? c.x + c.y : s.x;
        v.y = t1 ? c.z + c.w : s.y;
        *(float2*)(dst + p) = v;
        vA[j0] = v.x; vA[j0 + 1] = v.y;
        fA[j0] = t0;  fA[j0 + 1] = t1;
    }
    __syncthreads();

    // Levels 4..13 (node counts 512 .. 1 per block), src from sPre.
    float* vin = vA;  float* vout = vB;
    unsigned char* fin = fA; unsigned char* fout = fB;
    unsigned n = 512;
    unsigned soff = 3072;                     // sPre offset of level 4
    for (int L = 4; L <= 13; L++) {
        if (t < n) {
            unsigned j = t;
            unsigned p = (cap >> L) + b * n + j;
            bool tt = fin[2 * j] | fin[2 * j + 1];
            float v = tt ? vin[2 * j] + vin[2 * j + 1] : sPre[soff + j];
            dst[p] = v;
            vout[j] = v; fout[j] = (unsigned char)tt;
        }
        __syncthreads();
        soff += n; n >>= 1;
        float* tv = vin; vin = vout; vout = tv;
        unsigned char* tf = fin; fin = fout; fout = tf;
    }
    if (t == 0) g_f13[b] = fin[0];            // this subtree's level-13 flag

    // ---- last-block-done: the final block runs levels 14..23 ----
    __threadfence();                          // publish dst level-13 + g_f13
    __syncthreads();
    if (t == 0) {
        unsigned x = atomicAdd(&g_done, 1u);
        s_islast = (x == gridDim.x - 1u);
    }
    __syncthreads();
    if (!s_islast) return;
    __threadfence();                          // acquire other blocks' writes

    // Tail prefetch: src[0..1024) into sPre (covers levels 14..23 originals).
    if (t < 512u) {
        sPre[t] = __ldcs(src + t);
        sPre[512u + t] = __ldcs(src + 512u + t);
    }
    // Level 14: 512 nodes, children = level-13 values in dst (indices 1024+).
    if (t < 512u) {
        bool tt = g_f13[2 * t] | g_f13[2 * t + 1];
        unsigned p = 512u + t;
        float v = tt ? dst[2 * p] + dst[2 * p + 1] : sPre[p];  // own-thread sPre
        dst[p] = v;
        vA[t] = v; fA[t] = (unsigned char)tt;
    }
    __syncthreads();
    // Levels 15..23 (256 nodes down to the root), all in smem.
    for (unsigned m = 256; m >= 1; m >>= 1) {
        bool tt = false; float v = 0.0f;
        if (t < m) {
            tt = fA[2 * t] | fA[2 * t + 1];
            unsigned pp = m + t;
            v = tt ? vA[2 * t] + vA[2 * t + 1] : sPre[pp];
            dst[pp] = v;
        }
        __syncthreads();
        if (t < m) { vA[t] = v; fA[t] = (unsigned char)tt; }
        __syncthreads();
    }
    if (t == 0) {
        dst[0] = sPre[0];                     // untouched slot 0
        g_done = 0u;                          // reset for next replay
    }
}

extern "C" void kernel_launch(void* const* d_in, const int* in_sizes, int n_in,
                              void* d_out, int out_size) {
    // tree_values matches out_size; remaining two (metadata order) are
    // indices (int32) then values (float32).
    int ti = 0;
    for (int i = 0; i < n_in; i++) if (in_sizes[i] == out_size) { ti = i; break; }
    int others[2]; int c = 0;
    for (int i = 0; i < n_in && c < 2; i++) if (i != ti) others[c++] = i;

    const float* tree_in = (const float*)d_in[ti];
    const int*   indices = (const int*)d_in[others[0]];
    const float* values  = (const float*)d_in[others[1]];
    float* out = (float*)d_out;

    unsigned total = (unsigned)out_size;      // 16,777,216
    unsigned cap   = total >> 1;              // 8,388,608 = 2^23
    int n = in_sizes[others[0]];              // 1,048,576

    int n2 = n >> 1;                          // 2 updates per thread
    k_scatter<<<(n2 + 255) / 256, 256>>>((const int2*)indices,
                                         (const float2*)values, out, n2, cap);

    // k_prop via PDL: may launch while k_scatter still runs; its phase A is
    // scatter-independent, and it gates phase B with gridDepSync.
    unsigned nblocks = (cap >> 1) / CHUNK;    // 1024
    cudaLaunchConfig_t cfg = {};
    cfg.gridDim = dim3(nblocks, 1, 1);
    cfg.blockDim = dim3(PTHREADS, 1, 1);
    cfg.dynamicSmemBytes = 0;
    cfg.stream = 0;                           // same (legacy) stream as <<<>>>
    cudaLaunchAttribute attr[1];
    attr[0].id = cudaLaunchAttributeProgrammaticStreamSerialization;
    attr[0].val.programmaticStreamSerializationAllowed = 1;
    cfg.attrs = attr;
    cfg.numAttrs = 1;
    cudaLaunchKernelEx(&cfg, k_prop, out, tree_in, cap);
}